// round 9
// baseline (speedup 1.0000x reference)
#include <cuda_runtime.h>

// Pitch loss with PDL (programmatic dependent launch) to hide the zero-init
// node under the main kernel's launch ramp.
//
// Node 1 (pl_zero_kernel): stores out[0] = 0, then griddepcontrol
// .launch_dependents -- signals that the dependent grid may begin launching
// immediately; its writes are guaranteed visible to the dependent at
// griddepcontrol.wait.
//
// Node 2 (pitch_loss_kernel, launched with ProgrammaticStreamSerialization):
// launches concurrently with node 1's drain. Each 8-lane group handles one
// 32-frame note: one LDG.128 per lane per track (warp covers 512B contiguous
// per track, fully coalesced), 3 width-8 shuffles reduce the gen-t difference,
// leader tests |sum| > 0.5*len (no division). griddepcontrol.wait (satisfied
// long before -- the zero kernel is ~200ns) orders the zero store before the
// predicated fire-and-forget atomicAdd(out, 1/N), which compiles to REDG
// (return unused): no round trip, no completion tail.
//
// Determinism: contributions are exactly 2^-10; every partial sum m/1024
// (m <= 1024) is exactly representable in fp32 -> order-independent,
// bit-exact across graph replays.

__global__ void pl_zero_kernel(float* out) {
    if (threadIdx.x == 0) out[0] = 0.0f;
    asm volatile("griddepcontrol.launch_dependents;" ::: "memory");
}

__global__ void __launch_bounds__(256, 1)
pitch_loss_kernel(const float* __restrict__ gen_f0,
                  const float* __restrict__ t_f0,
                  const int*   __restrict__ onset,
                  const int*   __restrict__ offset,
                  float*       __restrict__ out,
                  int N) {
    const int lane  = threadIdx.x & 31;
    const int sub   = lane & 7;                       // float4 slot in note
    const int grp   = lane >> 3;                      // which of warp's 4 notes
    const int gwarp = (blockIdx.x * blockDim.x + threadIdx.x) >> 5;
    const int note  = gwarp * 4 + grp;

    bool hit = false;
    float inv_n = 1.0f / (float)N;

    if (note < N) {
        const int a   = onset[note];
        const int b   = offset[note];
        const int len = b - a;

        float d;
        if (len == 32 && (a & 3) == 0) {
            // Fast path: one float4 per lane per track covers the segment.
            const float4 g = ((const float4*)(gen_f0 + a))[sub];
            const float4 t = ((const float4*)(t_f0  + a))[sub];
            d = ((g.x - t.x) + (g.y - t.y)) + ((g.z - t.z) + (g.w - t.w));
        } else {
            // General path: strided scalar loads over the segment.
            d = 0.0f;
            for (int i = a + sub; i < b; i += 8)
                d += gen_f0[i] - t_f0[i];
        }

        // Reduce within the 8-lane group (width = 8).
        #pragma unroll
        for (int o = 4; o > 0; o >>= 1)
            d += __shfl_down_sync(0xFFFFFFFFu, d, o, 8);

        hit = (sub == 0) && (fabsf(d) > 0.5f * (float)len);
    }

    // Wait for the predecessor grid's memory (the zero store) to be visible.
    // By the time threads reach this, the zero kernel finished long ago, so
    // this is effectively free.
    asm volatile("griddepcontrol.wait;" ::: "memory");

    if (hit)
        atomicAdd(out, inv_n);   // return unused -> REDG (fire-and-forget)
}

extern "C" void kernel_launch(void* const* d_in, const int* in_sizes, int n_in,
                              void* d_out, int out_size) {
    const float* gen_f0 = (const float*)d_in[0];
    const float* t_f0   = (const float*)d_in[1];
    const int*   onset  = (const int*)d_in[2];
    const int*   offset = (const int*)d_in[3];
    float* out = (float*)d_out;

    const int N = in_sizes[2];   // number of notes (1024)

    // Node 1: zero the scalar output.
    pl_zero_kernel<<<1, 32>>>(out);

    // Node 2: main kernel, launched with programmatic stream serialization so
    // its grid launch overlaps node 1's execution (PDL edge in the graph).
    const int THREADS = 256;                                  // 8 warps/block
    const int warps   = (N + 3) / 4;                          // 4 notes/warp
    const int blocks  = (warps * 32 + THREADS - 1) / THREADS; // 32

    cudaLaunchConfig_t cfg = {};
    cfg.gridDim  = dim3((unsigned)blocks, 1, 1);
    cfg.blockDim = dim3(THREADS, 1, 1);
    cfg.dynamicSmemBytes = 0;
    cfg.stream = 0;

    cudaLaunchAttribute attrs[1];
    attrs[0].id = cudaLaunchAttributeProgrammaticStreamSerialization;
    attrs[0].val.programmaticStreamSerializationAllowed = 1;
    cfg.attrs = attrs;
    cfg.numAttrs = 1;

    cudaLaunchKernelEx(&cfg, pitch_loss_kernel,
                       gen_f0, t_f0, onset, offset, out, N);
}